// round 3
// baseline (speedup 1.0000x reference)
#include <cuda_runtime.h>

#define HW   (128*128)        // 16384 pixels per (b,c) plane
#define CHW  (64*HW)          // one batch image, 64 channels
#define NPIX (4*HW)           // total pixels across batch

// Scratch tensors (allocation-free rule: __device__ globals)
__device__ float g_Q[4*CHW];
__device__ float g_V[4*CHW];
__device__ float g_O[4*CHW];

// ---------------------------------------------------------------------------
// conv1x1: out[b,f,p] = sum_c w[f,c]*in[b,c,p] + bias[f] (+ resid[b,f,p])
// Block: 256 threads, tile = 64 features x 256 pixels.
// Thread: 8 features x 8 pixels (pixels strided by 32 -> conflict-free LDS,
// coalesced LDG/STG). 16 LDS : 64 FFMA per k-step.
// ---------------------------------------------------------------------------
__global__ void __launch_bounds__(256, 2) conv1x1_kernel(
    const float* __restrict__ in, const float* __restrict__ w,
    const float* __restrict__ bias, const float* __restrict__ resid,
    float* __restrict__ out)
{
    extern __shared__ float sm[];
    float* xs = sm;             // [64][256] activation tile
    float* ws = sm + 64*256;    // [64][64]  weights
    float* bs = ws + 64*64;     // [64]      bias

    int tid = threadIdx.x;
    for (int i = tid; i < 64*64; i += 256) ws[i] = w[i];
    if (tid < 64) bs[tid] = bias[tid];

    int pix0 = blockIdx.x * 256;        // 16384 % 256 == 0 -> tile within one batch
    int b    = pix0 >> 14;
    int p    = pix0 & (HW - 1);
    const float* inp = in + (size_t)b*CHW + p;

    for (int i = tid; i < 64*256; i += 256) {
        int c  = i >> 8;
        int px = i & 255;
        xs[i] = inp[c*HW + px];
    }
    __syncthreads();

    int fg   = tid >> 5;   // feature group: features fg*8 .. fg*8+7 (uniform per warp)
    int lane = tid & 31;   // pixel lane: pixels lane + 32*k

    float acc[8][8];
    #pragma unroll
    for (int j = 0; j < 8; j++)
        #pragma unroll
        for (int k = 0; k < 8; k++) acc[j][k] = 0.f;

    for (int c = 0; c < 64; c++) {
        float wv[8], xv[8];
        #pragma unroll
        for (int j = 0; j < 8; j++) wv[j] = ws[(fg*8 + j)*64 + c];   // broadcast
        #pragma unroll
        for (int k = 0; k < 8; k++) xv[k] = xs[c*256 + lane + 32*k]; // conflict-free
        #pragma unroll
        for (int j = 0; j < 8; j++)
            #pragma unroll
            for (int k = 0; k < 8; k++)
                acc[j][k] += wv[j]*xv[k];
    }

    float* outp = out + (size_t)b*CHW + p;
    const float* rp = resid ? (resid + (size_t)b*CHW + p) : nullptr;
    #pragma unroll
    for (int j = 0; j < 8; j++) {
        int f = fg*8 + j;
        float bv = bs[f];
        #pragma unroll
        for (int k = 0; k < 8; k++) {
            int px = lane + 32*k;
            float r = acc[j][k] + bv;
            if (rp) r += rp[f*HW + px];
            outp[f*HW + px] = r;
        }
    }
}

// ---------------------------------------------------------------------------
// Local attention (5x5 window, zero-padded):
//   A[k](p)   = sum_c Q[c,p+d_k] * Q[c,p];  A = softmax_k(A)
//   O[c](p)   = sum_k A[k](p) * V[c,p+d_k]
// Tile: interior 16h x 32w, halo 20 x 36 = 720 positions.
// smem: one [64][720] buffer (184.3KB), reused for Q then V.
// Thread: 2 vertically-adjacent pixels -> 6x5 shared window per channel
// (30 LDS feed 50 FFMA). All LDS conflict-free ([c][pos] layout, lanes walk pos).
// ---------------------------------------------------------------------------
#define HT 16
#define WT 32
#define HR (HT + 4)     // 20
#define WC (WT + 4)     // 36
#define NPOS (HR * WC)  // 720

__global__ void __launch_bounds__(256, 1) attn_kernel(
    const float* __restrict__ Q, const float* __restrict__ V,
    float* __restrict__ O)
{
    extern __shared__ float s[];   // [64][NPOS]

    int tid = threadIdx.x;
    int wx  = tid & 31;            // column within tile (lane -> coalesced)
    int hy  = tid >> 5;            // row pair: rows hy*2, hy*2+1
    int b   = blockIdx.z;
    int h0  = blockIdx.y * HT;
    int w0  = blockIdx.x * WT;

    // ---- load Q halo tile (zero padding at image borders) ----
    const float* Qb = Q + (size_t)b*CHW;
    for (int i = tid; i < 64*NPOS; i += 256) {
        int c   = i / NPOS;
        int pos = i - c*NPOS;
        int r   = pos / WC;
        int col = pos - r*WC;
        int gh  = h0 + r - 2;
        int gw  = w0 + col - 2;
        float v = 0.f;
        if ((unsigned)gh < 128u && (unsigned)gw < 128u)
            v = Qb[c*HW + gh*128 + gw];
        s[i] = v;
    }
    __syncthreads();

    int r0 = hy*2;
    float A1[25], A2[25];
    #pragma unroll
    for (int k = 0; k < 25; k++) { A1[k] = 0.f; A2[k] = 0.f; }

    for (int c = 0; c < 64; c++) {
        const float* qs = s + c*NPOS + r0*WC + wx;
        float n[6][5];
        #pragma unroll
        for (int j = 0; j < 6; j++)
            #pragma unroll
            for (int i = 0; i < 5; i++)
                n[j][i] = qs[j*WC + i];
        float q1 = n[2][2];   // center of pixel (h0+r0,   w0+wx)
        float q2 = n[3][2];   // center of pixel (h0+r0+1, w0+wx)
        #pragma unroll
        for (int j = 0; j < 5; j++)
            #pragma unroll
            for (int i = 0; i < 5; i++) {
                A1[j*5+i] += q1 * n[j][i];
                A2[j*5+i] += q2 * n[j+1][i];
            }
    }

    // ---- softmax over 25 neighbors ----
    {
        float m1 = A1[0], m2 = A2[0];
        #pragma unroll
        for (int k = 1; k < 25; k++) { m1 = fmaxf(m1, A1[k]); m2 = fmaxf(m2, A2[k]); }
        float s1 = 0.f, s2 = 0.f;
        #pragma unroll
        for (int k = 0; k < 25; k++) {
            A1[k] = __expf(A1[k] - m1); s1 += A1[k];
            A2[k] = __expf(A2[k] - m2); s2 += A2[k];
        }
        float i1 = 1.f/s1, i2 = 1.f/s2;
        #pragma unroll
        for (int k = 0; k < 25; k++) { A1[k] *= i1; A2[k] *= i2; }
    }

    __syncthreads();   // everyone done reading Q tile

    // ---- load V halo tile into the same buffer ----
    const float* Vb = V + (size_t)b*CHW;
    for (int i = tid; i < 64*NPOS; i += 256) {
        int c   = i / NPOS;
        int pos = i - c*NPOS;
        int r   = pos / WC;
        int col = pos - r*WC;
        int gh  = h0 + r - 2;
        int gw  = w0 + col - 2;
        float v = 0.f;
        if ((unsigned)gh < 128u && (unsigned)gw < 128u)
            v = Vb[c*HW + gh*128 + gw];
        s[i] = v;
    }
    __syncthreads();

    // ---- aggregate ----
    float* Ob = O + (size_t)b*CHW + (h0 + r0)*128 + (w0 + wx);
    for (int c = 0; c < 64; c++) {
        const float* vs = s + c*NPOS + r0*WC + wx;
        float n[6][5];
        #pragma unroll
        for (int j = 0; j < 6; j++)
            #pragma unroll
            for (int i = 0; i < 5; i++)
                n[j][i] = vs[j*WC + i];
        float o1 = 0.f, o2 = 0.f;
        #pragma unroll
        for (int j = 0; j < 5; j++)
            #pragma unroll
            for (int i = 0; i < 5; i++) {
                o1 += A1[j*5+i] * n[j][i];
                o2 += A2[j*5+i] * n[j+1][i];
            }
        Ob[c*HW]       = o1;
        Ob[c*HW + 128] = o2;
    }
}

// ---------------------------------------------------------------------------
extern "C" void kernel_launch(void* const* d_in, const int* in_sizes, int n_in,
                              void* d_out, int out_size)
{
    const float* x  = (const float*)d_in[0];
    const float* y  = (const float*)d_in[1];
    const float* wx = (const float*)d_in[2];
    const float* bx = (const float*)d_in[3];
    const float* wy = (const float*)d_in[4];
    const float* by = (const float*)d_in[5];
    const float* wo = (const float*)d_in[6];
    const float* bo = (const float*)d_in[7];
    float* out = (float*)d_out;

    void *pQ, *pV, *pO;
    cudaGetSymbolAddress(&pQ, g_Q);
    cudaGetSymbolAddress(&pV, g_V);
    cudaGetSymbolAddress(&pO, g_O);

    const int conv_smem = (64*256 + 64*64 + 64) * 4;   // 82176 B
    const int attn_smem = 64*NPOS*4;                   // 184320 B
    cudaFuncSetAttribute(conv1x1_kernel, cudaFuncAttributeMaxDynamicSharedMemorySize, conv_smem);
    cudaFuncSetAttribute(attn_kernel,   cudaFuncAttributeMaxDynamicSharedMemorySize, attn_smem);

    // q = wy @ y + by ; v = wx @ x + bx
    conv1x1_kernel<<<NPIX/256, 256, conv_smem>>>(y, wy, by, nullptr, (float*)pQ);
    conv1x1_kernel<<<NPIX/256, 256, conv_smem>>>(x, wx, bx, nullptr, (float*)pV);

    // scores + softmax + aggregate
    attn_kernel<<<dim3(128/WT, 128/HT, 4), 256, attn_smem>>>(
        (const float*)pQ, (const float*)pV, (float*)pO);

    // out = wo @ O + bo + x
    conv1x1_kernel<<<NPIX/256, 256, conv_smem>>>((const float*)pO, wo, bo, x, out);
}